// round 1
// baseline (speedup 1.0000x reference)
#include <cuda_runtime.h>

// Problem constants
#define BATCH   2
#define HEADS   16
#define SEQ     2048
#define HD      64
#define DMODEL  1024
#define MROWS   (BATCH * SEQ)   // 4096

// Scratch (allocation-free rule: __device__ globals)
__device__ float g_Q[BATCH * HEADS * SEQ * HD];   // [B,H,S,HD]
__device__ float g_K[BATCH * HEADS * SEQ * HD];
__device__ float g_V[BATCH * HEADS * SEQ * HD];
__device__ float g_O[BATCH * SEQ * DMODEL];       // [B,S,D]

// ---------------------------------------------------------------------------
// GEMM: out = A[M,K] @ W[N,K]^T + bias      (M=4096, N=K=1024)
// mode 1/2/3: write Q/K/V in [B,H,S,HD] head layout (A = x)
// mode 0:     A := g_O, write flat [M,N] to out (final projection)
// Tiles: BM=BN=128, BK=16, 256 threads, 8x8 micro-tile, sw-pipelined loads.
// ---------------------------------------------------------------------------
__global__ __launch_bounds__(256) void gemm_kernel(
    const float* __restrict__ A_in,
    const float* __restrict__ W,
    const float* __restrict__ bias,
    float* __restrict__ out,
    int mode)
{
    const int K = DMODEL;
    const int N = DMODEL;
    const float* A = (mode == 0) ? (const float*)g_O : A_in;

    __shared__ float As[16 * 132];
    __shared__ float Bs[16 * 132];

    const int tid  = threadIdx.x;
    const int row0 = blockIdx.y * 128;
    const int col0 = blockIdx.x * 128;
    const int tx = tid & 15;
    const int ty = tid >> 4;

    float acc[8][8];
#pragma unroll
    for (int i = 0; i < 8; i++)
#pragma unroll
        for (int j = 0; j < 8; j++) acc[i][j] = 0.0f;

    // Per-thread load slots: i in {0,1}; f = tid + i*256
    // r = f>>2 (tile row 0..127), kk = (f&3)*4 (k offset 0,4,8,12)
    float4 ra[2], rb[2];

    // Preload first k-tile
#pragma unroll
    for (int i = 0; i < 2; i++) {
        int f  = tid + i * 256;
        int r  = f >> 2;
        int kk = (f & 3) * 4;
        ra[i] = *(const float4*)(A + (size_t)(row0 + r) * K + kk);
        rb[i] = *(const float4*)(W + (size_t)(col0 + r) * K + kk);
    }

    for (int kt = 0; kt < K; kt += 16) {
        // store staged regs to smem
#pragma unroll
        for (int i = 0; i < 2; i++) {
            int f  = tid + i * 256;
            int r  = f >> 2;
            int kk = (f & 3) * 4;
            As[(kk + 0) * 132 + r] = ra[i].x;
            As[(kk + 1) * 132 + r] = ra[i].y;
            As[(kk + 2) * 132 + r] = ra[i].z;
            As[(kk + 3) * 132 + r] = ra[i].w;
            Bs[(kk + 0) * 132 + r] = rb[i].x;
            Bs[(kk + 1) * 132 + r] = rb[i].y;
            Bs[(kk + 2) * 132 + r] = rb[i].z;
            Bs[(kk + 3) * 132 + r] = rb[i].w;
        }
        __syncthreads();

        // prefetch next k-tile (overlaps with compute below)
        if (kt + 16 < K) {
#pragma unroll
            for (int i = 0; i < 2; i++) {
                int f  = tid + i * 256;
                int r  = f >> 2;
                int kk = (f & 3) * 4;
                ra[i] = *(const float4*)(A + (size_t)(row0 + r) * K + kt + 16 + kk);
                rb[i] = *(const float4*)(W + (size_t)(col0 + r) * K + kt + 16 + kk);
            }
        }

#pragma unroll
        for (int k = 0; k < 16; k++) {
            __align__(16) float a[8];
            __align__(16) float b[8];
            *(float4*)(a)     = *(const float4*)(As + k * 132 + ty * 4);
            *(float4*)(a + 4) = *(const float4*)(As + k * 132 + 64 + ty * 4);
            *(float4*)(b)     = *(const float4*)(Bs + k * 132 + tx * 4);
            *(float4*)(b + 4) = *(const float4*)(Bs + k * 132 + 64 + tx * 4);
#pragma unroll
            for (int i = 0; i < 8; i++)
#pragma unroll
                for (int j = 0; j < 8; j++)
                    acc[i][j] += a[i] * b[j];
        }
        __syncthreads();
    }

    // Epilogue
#pragma unroll
    for (int i = 0; i < 8; i++) {
        int m = row0 + ((i >> 2) << 6) + ty * 4 + (i & 3);
#pragma unroll
        for (int j = 0; j < 8; j++) {
            int n = col0 + ((j >> 2) << 6) + tx * 4 + (j & 3);
            float v = acc[i][j] + bias[n];
            if (mode == 0) {
                out[(size_t)m * N + n] = v;
            } else {
                int h = n >> 6, d = n & 63;
                int b = m >> 11, s = m & 2047;
                float* dst = (mode == 1) ? g_Q : (mode == 2) ? g_K : g_V;
                dst[(((size_t)(b * HEADS + h)) * SEQ + s) * HD + d] = v;
            }
        }
    }
}

// ---------------------------------------------------------------------------
// Flash attention, fp32. Grid: (SEQ/64, B*H). 256 threads.
// Per CTA: 64 queries x full sequence in 64-key chunks, online softmax.
// smem tiles stride 68 (pad) -> conflict-free float4 LDS everywhere.
// Thread map: ti=tid>>4 (query rows 4*ti..+3), tj=tid&15.
//  scores phase: key cols j in {tj, tj+16, tj+32, tj+48} (bank-spread)
//  AV phase:     out cols  dv in {4*tj..4*tj+3} (contiguous float4)
// ---------------------------------------------------------------------------
__global__ __launch_bounds__(256) void attn_kernel()
{
    extern __shared__ float sm[];
    float* Qs = sm;                 // [64][68]
    float* Ks = sm + 64 * 68;
    float* Vs = sm + 2 * 64 * 68;
    float* Ps = sm + 3 * 64 * 68;

    const int tid = threadIdx.x;
    const int ti = tid >> 4;
    const int tj = tid & 15;
    const int qt = blockIdx.x;      // query tile 0..31
    const int bh = blockIdx.y;      // 0..31

    const float* Qb = g_Q + ((size_t)bh * SEQ + qt * 64) * HD;
    const float* Kb = g_K + (size_t)bh * SEQ * HD;
    const float* Vb = g_V + (size_t)bh * SEQ * HD;

    // Load Q tile
#pragma unroll
    for (int i = 0; i < 4; i++) {
        int f  = tid + i * 256;
        int r  = f >> 4;
        int d0 = (f & 15) * 4;
        *(float4*)(Qs + r * 68 + d0) = *(const float4*)(Qb + r * HD + d0);
    }

    float m[4], l[4], o[4][4];
#pragma unroll
    for (int r = 0; r < 4; r++) {
        m[r] = -1e30f;
        l[r] = 0.0f;
#pragma unroll
        for (int c = 0; c < 4; c++) o[r][c] = 0.0f;
    }

    const float scale = 0.125f;   // 1/sqrt(64)

    for (int ck = 0; ck < SEQ / 64; ck++) {
        const float* Kc = Kb + (size_t)ck * 64 * HD;
        const float* Vc = Vb + (size_t)ck * 64 * HD;
#pragma unroll
        for (int i = 0; i < 4; i++) {
            int f  = tid + i * 256;
            int r  = f >> 4;
            int d0 = (f & 15) * 4;
            *(float4*)(Ks + r * 68 + d0) = *(const float4*)(Kc + r * HD + d0);
            *(float4*)(Vs + r * 68 + d0) = *(const float4*)(Vc + r * HD + d0);
        }
        __syncthreads();

        // --- scores: S[4r][4c] over keys j = tj + 16*c ---
        float s[4][4];
#pragma unroll
        for (int r = 0; r < 4; r++)
#pragma unroll
            for (int c = 0; c < 4; c++) s[r][c] = 0.0f;

#pragma unroll
        for (int d0 = 0; d0 < 64; d0 += 4) {
            __align__(16) float qa[4][4];
            __align__(16) float ka[4][4];
#pragma unroll
            for (int r = 0; r < 4; r++)
                *(float4*)qa[r] = *(const float4*)(Qs + (4 * ti + r) * 68 + d0);
#pragma unroll
            for (int c = 0; c < 4; c++)
                *(float4*)ka[c] = *(const float4*)(Ks + (tj + 16 * c) * 68 + d0);
#pragma unroll
            for (int r = 0; r < 4; r++)
#pragma unroll
                for (int c = 0; c < 4; c++)
#pragma unroll
                    for (int e = 0; e < 4; e++)
                        s[r][c] += qa[r][e] * ka[c][e];
        }

        // --- online softmax (reduce across the 16 tj lanes) ---
#pragma unroll
        for (int r = 0; r < 4; r++) {
            float rmax = -1e30f;
#pragma unroll
            for (int c = 0; c < 4; c++) {
                s[r][c] *= scale;
                rmax = fmaxf(rmax, s[r][c]);
            }
#pragma unroll
            for (int off = 1; off < 16; off <<= 1)
                rmax = fmaxf(rmax, __shfl_xor_sync(0xffffffffu, rmax, off));
            float mnew  = fmaxf(m[r], rmax);
            float alpha = __expf(m[r] - mnew);
            float rsum = 0.0f;
#pragma unroll
            for (int c = 0; c < 4; c++) {
                float p = __expf(s[r][c] - mnew);
                s[r][c] = p;
                rsum += p;
            }
#pragma unroll
            for (int off = 1; off < 16; off <<= 1)
                rsum += __shfl_xor_sync(0xffffffffu, rsum, off);
            l[r] = l[r] * alpha + rsum;
            m[r] = mnew;
#pragma unroll
            for (int c = 0; c < 4; c++) o[r][c] *= alpha;
            // stash P (row 4ti+r, col tj+16c)
#pragma unroll
            for (int c = 0; c < 4; c++)
                Ps[(4 * ti + r) * 68 + tj + 16 * c] = s[r][c];
        }
        __syncthreads();

        // --- AV: O[4r][4*tj + c] += P[row][j] * V[j][4*tj + c] ---
#pragma unroll
        for (int j0 = 0; j0 < 64; j0 += 4) {
            __align__(16) float va[4][4];
            __align__(16) float pa[4][4];
#pragma unroll
            for (int jj = 0; jj < 4; jj++)
                *(float4*)va[jj] = *(const float4*)(Vs + (j0 + jj) * 68 + 4 * tj);
#pragma unroll
            for (int r = 0; r < 4; r++)
                *(float4*)pa[r] = *(const float4*)(Ps + (4 * ti + r) * 68 + j0);
#pragma unroll
            for (int r = 0; r < 4; r++)
#pragma unroll
                for (int jj = 0; jj < 4; jj++)
#pragma unroll
                    for (int c = 0; c < 4; c++)
                        o[r][c] += pa[r][jj] * va[jj][c];
        }
        __syncthreads();
    }

    // Write O tile (to [B,S,D] layout)
    const int b = bh >> 4;
    const int h = bh & 15;
#pragma unroll
    for (int r = 0; r < 4; r++) {
        float inv = 1.0f / l[r];
        int srow = qt * 64 + 4 * ti + r;
        float4 res;
        res.x = o[r][0] * inv;
        res.y = o[r][1] * inv;
        res.z = o[r][2] * inv;
        res.w = o[r][3] * inv;
        *(float4*)(g_O + ((size_t)(b * SEQ + srow)) * DMODEL + h * HD + 4 * tj) = res;
    }
}

// ---------------------------------------------------------------------------
extern "C" void kernel_launch(void* const* d_in, const int* in_sizes, int n_in,
                              void* d_out, int out_size)
{
    const float* x  = (const float*)d_in[0];
    const float* Wq = (const float*)d_in[1];
    const float* bq = (const float*)d_in[2];
    const float* Wk = (const float*)d_in[3];
    const float* bk = (const float*)d_in[4];
    const float* Wv = (const float*)d_in[5];
    const float* bv = (const float*)d_in[6];
    const float* Wo = (const float*)d_in[7];
    const float* bo = (const float*)d_in[8];
    float* out = (float*)d_out;

    dim3 ggrid(DMODEL / 128, MROWS / 128);   // (8, 32)

    // QKV projections (write head-major scratch)
    gemm_kernel<<<ggrid, 256>>>(x, Wq, bq, nullptr, 1);
    gemm_kernel<<<ggrid, 256>>>(x, Wk, bk, nullptr, 2);
    gemm_kernel<<<ggrid, 256>>>(x, Wv, bv, nullptr, 3);

    // Attention
    const int smem = 4 * 64 * 68 * sizeof(float);   // 69632 B
    static int attr_set = 0;
    if (!attr_set) {
        cudaFuncSetAttribute(attn_kernel,
                             cudaFuncAttributeMaxDynamicSharedMemorySize, smem);
        attr_set = 1;
    }
    attn_kernel<<<dim3(SEQ / 64, BATCH * HEADS), 256, smem>>>();

    // Output projection (reads g_O, writes d_out)
    gemm_kernel<<<ggrid, 256>>>(nullptr, Wo, bo, out, 0);
}

// round 4
// speedup vs baseline: 2.2062x; 2.2062x over previous
#include <cuda_runtime.h>
#include <cuda_bf16.h>
#include <cstdint>

// Problem constants
#define BATCH   2
#define HEADS   16
#define SEQ     2048
#define HD      64
#define DMODEL  1024
#define MROWS   (BATCH * SEQ)   // 4096

// ===========================================================================
// Global scratch (allocation-free rule: __device__ globals). bf16 hi/lo planes.
// ===========================================================================
__device__ __nv_bfloat16 g_xh[MROWS * DMODEL], g_xl[MROWS * DMODEL];
__device__ __nv_bfloat16 g_Wqh[DMODEL * DMODEL], g_Wql[DMODEL * DMODEL];
__device__ __nv_bfloat16 g_Wkh[DMODEL * DMODEL], g_Wkl[DMODEL * DMODEL];
__device__ __nv_bfloat16 g_Wvh[DMODEL * DMODEL], g_Wvl[DMODEL * DMODEL];
__device__ __nv_bfloat16 g_Woh[DMODEL * DMODEL], g_Wol[DMODEL * DMODEL];
// Q/K/V head-major [B,H,S,HD]
__device__ __nv_bfloat16 g_Qh[MROWS * DMODEL], g_Ql[MROWS * DMODEL];
__device__ __nv_bfloat16 g_Kh[MROWS * DMODEL], g_Kl[MROWS * DMODEL];
__device__ __nv_bfloat16 g_Vh[MROWS * DMODEL], g_Vl[MROWS * DMODEL];
// attention output [B,S,D]
__device__ __nv_bfloat16 g_Oh[MROWS * DMODEL], g_Ol[MROWS * DMODEL];

// ===========================================================================
// PTX helpers
// ===========================================================================
__device__ __forceinline__ void mma_bf16(float* c, const uint32_t* a,
                                         const uint32_t* b) {
    asm volatile(
        "mma.sync.aligned.m16n8k16.row.col.f32.bf16.bf16.f32 "
        "{%0,%1,%2,%3}, {%4,%5,%6,%7}, {%8,%9}, {%0,%1,%2,%3};\n"
        : "+f"(c[0]), "+f"(c[1]), "+f"(c[2]), "+f"(c[3])
        : "r"(a[0]), "r"(a[1]), "r"(a[2]), "r"(a[3]),
          "r"(b[0]), "r"(b[1]));
}

__device__ __forceinline__ void ldsm_x2_t(uint32_t& r0, uint32_t& r1,
                                          uint32_t addr) {
    asm volatile(
        "ldmatrix.sync.aligned.m8n8.x2.trans.shared.b16 {%0,%1}, [%2];"
        : "=r"(r0), "=r"(r1) : "r"(addr));
}

__device__ __forceinline__ uint32_t smem_u32(const void* p) {
    uint32_t a;
    asm("{ .reg .u64 t; cvta.to.shared.u64 t, %1; cvt.u32.u64 %0, t; }"
        : "=r"(a) : "l"(p));
    return a;
}

__device__ __forceinline__ void cp_async16(uint32_t dst, const void* src) {
    asm volatile("cp.async.cg.shared.global [%0], [%1], 16;"
                 :: "r"(dst), "l"(src));
}
__device__ __forceinline__ void cp_commit() {
    asm volatile("cp.async.commit_group;");
}
template <int N> __device__ __forceinline__ void cp_wait() {
    asm volatile("cp.async.wait_group %0;" :: "n"(N));
}

// split two fp32 into packed bf16x2 hi + lo
__device__ __forceinline__ void split2(float x, float y,
                                       uint32_t& hi, uint32_t& lo) {
    __nv_bfloat16 hx = __float2bfloat16(x);
    __nv_bfloat16 hy = __float2bfloat16(y);
    __nv_bfloat162 h = __halves2bfloat162(hx, hy);
    __nv_bfloat162 l = __halves2bfloat162(
        __float2bfloat16(x - __bfloat162float(hx)),
        __float2bfloat16(y - __bfloat162float(hy)));
    hi = *(uint32_t*)&h;
    lo = *(uint32_t*)&l;
}

// ===========================================================================
// Split fp32 tensor -> bf16 hi/lo planes. which: 0=x 1=Wq 2=Wk 3=Wv 4=Wo
// ===========================================================================
__global__ __launch_bounds__(256) void split_kernel(
    const float* __restrict__ src, int which, int n4)
{
    __nv_bfloat16 *hi, *lo;
    switch (which) {
        case 0: hi = g_xh;  lo = g_xl;  break;
        case 1: hi = g_Wqh; lo = g_Wql; break;
        case 2: hi = g_Wkh; lo = g_Wkl; break;
        case 3: hi = g_Wvh; lo = g_Wvl; break;
        default: hi = g_Woh; lo = g_Wol; break;
    }
    int i = blockIdx.x * blockDim.x + threadIdx.x;
    if (i >= n4) return;
    float4 v = ((const float4*)src)[i];
    uint32_t h0, l0, h1, l1;
    split2(v.x, v.y, h0, l0);
    split2(v.z, v.w, h1, l1);
    ((uint32_t*)hi)[2 * i + 0] = h0;
    ((uint32_t*)hi)[2 * i + 1] = h1;
    ((uint32_t*)lo)[2 * i + 0] = l0;
    ((uint32_t*)lo)[2 * i + 1] = l1;
}

// ===========================================================================
// bf16x2 GEMM: out = A[M,K] @ W[N,K]^T + bias  (M=4096, N=K=1024)
// CTA 128x128, BK=32, 256 threads (8 warps 4m x 2n, warp tile 32x64).
// Smem planes [row][40 bf16] (80B stride -> conflict-free fragment LDS).
// mode 1/2/3: A=x planes, W=Wq/Wk/Wv, write Q/K/V hi/lo planes [B,H,S,HD]
// mode 0:     A=g_O planes, W=Wo, write fp32 out [M,N]
// ===========================================================================
#define GPLB 10240                 // plane bytes: 128 * 40 * 2
#define GSTAGE (4 * GPLB)          // 40960
#define G_SMEM (2 * GSTAGE)        // 81920

__global__ __launch_bounds__(256, 2) void gemm_bf16x2(
    const float* __restrict__ bias, float* __restrict__ out, int mode)
{
    extern __shared__ char sm[];
    const uint32_t sbase = smem_u32(sm);

    const __nv_bfloat16 *Agh, *Agl, *Bgh, *Bgl;
    if (mode == 0)      { Agh = g_Oh; Agl = g_Ol; Bgh = g_Woh; Bgl = g_Wol; }
    else if (mode == 1) { Agh = g_xh; Agl = g_xl; Bgh = g_Wqh; Bgl = g_Wql; }
    else if (mode == 2) { Agh = g_xh; Agl = g_xl; Bgh = g_Wkh; Bgl = g_Wkl; }
    else                { Agh = g_xh; Agl = g_xl; Bgh = g_Wvh; Bgl = g_Wvl; }

    const int tid  = threadIdx.x;
    const int lane = tid & 31;
    const int wid  = tid >> 5;
    const int wm   = wid & 3;
    const int wn   = wid >> 2;
    const int g    = lane >> 2;
    const int t    = lane & 3;
    const int row0 = blockIdx.y * 128;
    const int col0 = blockIdx.x * 128;

    float acc[2][8][4];
#pragma unroll
    for (int i = 0; i < 2; i++)
#pragma unroll
        for (int j = 0; j < 8; j++)
#pragma unroll
            for (int q = 0; q < 4; q++) acc[i][j][q] = 0.0f;

    auto ld_stage = [&](int s, int kt) {
        const int kb = kt * 32;
        const uint32_t sb2 = sbase + s * GSTAGE;
#pragma unroll
        for (int i = 0; i < 2; i++) {
            int f = tid + i * 256;
            int r = f >> 2;
            int c = (f & 3) * 8;
            uint32_t o2 = (uint32_t)(r * 80 + c * 2);
            size_t ga = (size_t)(row0 + r) * DMODEL + kb + c;
            size_t gb = (size_t)(col0 + r) * DMODEL + kb + c;
            cp_async16(sb2 + o2,             Agh + ga);
            cp_async16(sb2 + GPLB + o2,      Agl + ga);
            cp_async16(sb2 + 2 * GPLB + o2,  Bgh + gb);
            cp_async16(sb2 + 3 * GPLB + o2,  Bgl + gb);
        }
    };

    ld_stage(0, 0);
    cp_commit();

    const int NS = DMODEL / 32;   // 32
    for (int kt = 0; kt < NS; kt++) {
        if (kt + 1 < NS) {
            ld_stage((kt + 1) & 1, kt + 1);
            cp_commit();
            cp_wait<1>();
        } else {
            cp_wait<0>();
        }
        __syncthreads();

        const char* st  = sm + (kt & 1) * GSTAGE;
        const char* sAh = st;
        const char* sAl = st + GPLB;
        const char* sBh = st + 2 * GPLB;
        const char* sBl = st + 3 * GPLB;

#pragma unroll
        for (int kk = 0; kk < 2; kk++) {
            uint32_t ah[2][4], al[2][4];
#pragma unroll
            for (int mt = 0; mt < 2; mt++) {
                int base = ((wm * 32 + mt * 16 + g) * 40 + kk * 16 + 2 * t) * 2;
                ah[mt][0] = *(const uint32_t*)(sAh + base);
                ah[mt][1] = *(const uint32_t*)(sAh + base + 640);
                ah[mt][2] = *(const uint32_t*)(sAh + base + 16);
                ah[mt][3] = *(const uint32_t*)(sAh + base + 656);
                al[mt][0] = *(const uint32_t*)(sAl + base);
                al[mt][1] = *(const uint32_t*)(sAl + base + 640);
                al[mt][2] = *(const uint32_t*)(sAl + base + 16);
                al[mt][3] = *(const uint32_t*)(sAl + base + 656);
            }
#pragma unroll
            for (int nt = 0; nt < 8; nt++) {
                int nb = ((wn * 64 + nt * 8 + g) * 40 + kk * 16 + 2 * t) * 2;
                uint32_t bh[2], bl[2];
                bh[0] = *(const uint32_t*)(sBh + nb);
                bh[1] = *(const uint32_t*)(sBh + nb + 16);
                bl[0] = *(const uint32_t*)(sBl + nb);
                bl[1] = *(const uint32_t*)(sBl + nb + 16);
#pragma unroll
                for (int mt = 0; mt < 2; mt++) {
                    mma_bf16(acc[mt][nt], ah[mt], bh);
                    mma_bf16(acc[mt][nt], ah[mt], bl);
                    mma_bf16(acc[mt][nt], al[mt], bh);
                }
            }
        }
        __syncthreads();
    }

    // Epilogue
    __nv_bfloat16* Dh = (mode == 1) ? g_Qh : (mode == 2) ? g_Kh : g_Vh;
    __nv_bfloat16* Dl = (mode == 1) ? g_Ql : (mode == 2) ? g_Kl : g_Vl;
#pragma unroll
    for (int mt = 0; mt < 2; mt++) {
#pragma unroll
        for (int h = 0; h < 2; h++) {
            const int m = row0 + wm * 32 + mt * 16 + g + h * 8;
            const int b_ = m >> 11;
            const int s_ = m & 2047;
#pragma unroll
            for (int nt = 0; nt < 8; nt++) {
                const int n = col0 + wn * 64 + nt * 8 + 2 * t;
                float vx = acc[mt][nt][h * 2 + 0] + bias[n + 0];
                float vy = acc[mt][nt][h * 2 + 1] + bias[n + 1];
                if (mode == 0) {
                    float2 v; v.x = vx; v.y = vy;
                    *(float2*)(out + (size_t)m * DMODEL + n) = v;
                } else {
                    const int hh = n >> 6, d = n & 63;
                    size_t idx = (((size_t)(b_ * HEADS + hh)) * SEQ + s_) * HD + d;
                    uint32_t hi, lo;
                    split2(vx, vy, hi, lo);
                    *(uint32_t*)(Dh + idx) = hi;
                    *(uint32_t*)(Dl + idx) = lo;
                }
            }
        }
    }
}

// ===========================================================================
// Flash attention, bf16x2 mma. Grid (SEQ/128, B*H), 256 threads (8 warps).
// Warp w owns query rows w*16..w*16+15; softmax warp-local. Key chunks of 64,
// cp.async double-buffered. All smem planes stride 72 bf16 (144B).
// ===========================================================================
#define A_QH 0
#define A_QL 18432
#define A_ST(st) (36864 + (st) * 36864)   // stage: Kh,Kl,Vh,Vl each 9216
#define A_PH 110592
#define A_PL 129024
#define ATT_SMEM 147456

__global__ __launch_bounds__(256, 1) void attn_bf16x2()
{
    extern __shared__ char sm[];
    const uint32_t sb = smem_u32(sm);

    const int tid  = threadIdx.x;
    const int lane = tid & 31;
    const int wid  = tid >> 5;
    const int g    = lane >> 2;
    const int t    = lane & 3;
    const int qt   = blockIdx.x;   // 0..15
    const int bh   = blockIdx.y;   // 0..31

    // Load Q planes (plain vector loads, once)
    {
        const __nv_bfloat16* qh = g_Qh + ((size_t)bh * SEQ + qt * 128) * HD;
        const __nv_bfloat16* ql = g_Ql + ((size_t)bh * SEQ + qt * 128) * HD;
#pragma unroll
        for (int i = 0; i < 4; i++) {
            int f = tid + i * 256;
            int r = f >> 3, c = f & 7;
            *(uint4*)(sm + A_QH + r * 144 + c * 16) =
                *(const uint4*)(qh + r * 64 + c * 8);
            *(uint4*)(sm + A_QL + r * 144 + c * 16) =
                *(const uint4*)(ql + r * 64 + c * 8);
        }
    }

    auto ld_kv = [&](int st, int ck) {
        const size_t go = ((size_t)bh * SEQ + (size_t)ck * 64) * HD;
        const uint32_t base = sb + A_ST(st);
#pragma unroll
        for (int i = 0; i < 2; i++) {
            int f = tid + i * 256;
            int r = f >> 3, c = f & 7;
            uint32_t o2 = (uint32_t)(r * 144 + c * 16);
            size_t gi = go + r * 64 + c * 8;
            cp_async16(base + o2,          g_Kh + gi);
            cp_async16(base + 9216 + o2,   g_Kl + gi);
            cp_async16(base + 18432 + o2,  g_Vh + gi);
            cp_async16(base + 27648 + o2,  g_Vl + gi);
        }
    };

    ld_kv(0, 0); cp_commit();
    ld_kv(1, 1); cp_commit();

    float o[8][4];
#pragma unroll
    for (int nt = 0; nt < 8; nt++)
#pragma unroll
        for (int q = 0; q < 4; q++) o[nt][q] = 0.0f;
    float mrow[2] = {-1e30f, -1e30f};
    float lrow[2] = {0.0f, 0.0f};
    const float scale = 0.125f;

    for (int ck = 0; ck < SEQ / 64; ck++) {
        if (ck >= SEQ / 64 - 2) cp_wait<0>(); else cp_wait<1>();
        __syncthreads();

        const char* kstg = sm + A_ST(ck & 1);
        const char* kh = kstg;
        const char* kl = kstg + 9216;
        const uint32_t vbase = sb + A_ST(ck & 1) + 18432;   // Vh; Vl = +9216

        // ---- QK^T ----
        float s[8][4];
#pragma unroll
        for (int nt = 0; nt < 8; nt++)
#pragma unroll
            for (int q = 0; q < 4; q++) s[nt][q] = 0.0f;

#pragma unroll
        for (int kk = 0; kk < 4; kk++) {
            int abase = ((wid * 16 + g) * 72 + kk * 16 + 2 * t) * 2;
            uint32_t ah[4], al[4];
            ah[0] = *(const uint32_t*)(sm + A_QH + abase);
            ah[1] = *(const uint32_t*)(sm + A_QH + abase + 1152);
            ah[2] = *(const uint32_t*)(sm + A_QH + abase + 16);
            ah[3] = *(const uint32_t*)(sm + A_QH + abase + 1168);
            al[0] = *(const uint32_t*)(sm + A_QL + abase);
            al[1] = *(const uint32_t*)(sm + A_QL + abase + 1152);
            al[2] = *(const uint32_t*)(sm + A_QL + abase + 16);
            al[3] = *(const uint32_t*)(sm + A_QL + abase + 1168);
#pragma unroll
            for (int nt = 0; nt < 8; nt++) {
                int nb = ((nt * 8 + g) * 72 + kk * 16 + 2 * t) * 2;
                uint32_t bh[2], bl[2];
                bh[0] = *(const uint32_t*)(kh + nb);
                bh[1] = *(const uint32_t*)(kh + nb + 16);
                bl[0] = *(const uint32_t*)(kl + nb);
                bl[1] = *(const uint32_t*)(kl + nb + 16);
                mma_bf16(s[nt], ah, bh);
                mma_bf16(s[nt], ah, bl);
                mma_bf16(s[nt], al, bh);
            }
        }

        // ---- online softmax (rows g, g+8; warp-local) + P split/store ----
#pragma unroll
        for (int nt = 0; nt < 8; nt++)
#pragma unroll
            for (int q = 0; q < 4; q++) s[nt][q] *= scale;

#pragma unroll
        for (int h = 0; h < 2; h++) {
            float mx = -1e30f;
#pragma unroll
            for (int nt = 0; nt < 8; nt++) {
                mx = fmaxf(mx, s[nt][h * 2 + 0]);
                mx = fmaxf(mx, s[nt][h * 2 + 1]);
            }
            mx = fmaxf(mx, __shfl_xor_sync(0xffffffffu, mx, 1));
            mx = fmaxf(mx, __shfl_xor_sync(0xffffffffu, mx, 2));
            const float mnew  = fmaxf(mrow[h], mx);
            const float alpha = __expf(mrow[h] - mnew);
            float rsum = 0.0f;
#pragma unroll
            for (int nt = 0; nt < 8; nt++) {
                float p0 = __expf(s[nt][h * 2 + 0] - mnew);
                float p1 = __expf(s[nt][h * 2 + 1] - mnew);
                s[nt][h * 2 + 0] = p0;
                s[nt][h * 2 + 1] = p1;
                rsum += p0 + p1;
            }
            rsum += __shfl_xor_sync(0xffffffffu, rsum, 1);
            rsum += __shfl_xor_sync(0xffffffffu, rsum, 2);
            lrow[h] = lrow[h] * alpha + rsum;
            mrow[h] = mnew;
#pragma unroll
            for (int nt = 0; nt < 8; nt++) {
                o[nt][h * 2 + 0] *= alpha;
                o[nt][h * 2 + 1] *= alpha;
            }
            const int r = wid * 16 + g + h * 8;
#pragma unroll
            for (int nt = 0; nt < 8; nt++) {
                uint32_t hi, lo;
                split2(s[nt][h * 2 + 0], s[nt][h * 2 + 1], hi, lo);
                int po = (r * 72 + nt * 8 + 2 * t) * 2;
                *(uint32_t*)(sm + A_PH + po) = hi;
                *(uint32_t*)(sm + A_PL + po) = lo;
            }
        }
        __syncwarp();   // P produced and consumed within this warp

        // ---- O += P @ V  (V via ldmatrix.trans) ----
#pragma unroll
        for (int kk = 0; kk < 4; kk++) {
            int pbase = ((wid * 16 + g) * 72 + kk * 16 + 2 * t) * 2;
            uint32_t ph[4], pl[4];
            ph[0] = *(const uint32_t*)(sm + A_PH + pbase);
            ph[1] = *(const uint32_t*)(sm + A_PH + pbase + 1152);
            ph[2] = *(const uint32_t*)(sm + A_PH + pbase + 16);
            ph[3] = *(const uint32_t*)(sm + A_PH + pbase + 1168);
            pl[0] = *(const uint32_t*)(sm + A_PL + pbase);
            pl[1] = *(const uint32_t*)(sm + A_PL + pbase + 1152);
            pl[2] = *(const uint32_t*)(sm + A_PL + pbase + 16);
            pl[3] = *(const uint32_t*)(sm + A_PL + pbase + 1168);
            const uint32_t vrow = vbase + (kk * 16 + (lane & 15)) * 144;
#pragma unroll
            for (int nt = 0; nt < 8; nt++) {
                uint32_t bh[2], bl[2];
                ldsm_x2_t(bh[0], bh[1], vrow + nt * 16);
                ldsm_x2_t(bl[0], bl[1], vrow + 9216 + nt * 16);
                mma_bf16(o[nt], ph, bh);
                mma_bf16(o[nt], ph, bl);
                mma_bf16(o[nt], pl, bh);
            }
        }
        __syncthreads();
        if (ck + 2 < SEQ / 64) { ld_kv(ck & 1, ck + 2); cp_commit(); }
    }

    // ---- epilogue: split & write to g_O planes [B,S,D] ----
    const int b_ = bh >> 4;
    const int h_ = bh & 15;
#pragma unroll
    for (int h = 0; h < 2; h++) {
        const float inv = 1.0f / lrow[h];
        const int srow = qt * 128 + wid * 16 + g + h * 8;
        const size_t ro = ((size_t)(b_ * SEQ + srow)) * DMODEL + h_ * 64;
#pragma unroll
        for (int nt = 0; nt < 8; nt++) {
            float vx = o[nt][h * 2 + 0] * inv;
            float vy = o[nt][h * 2 + 1] * inv;
            uint32_t hi, lo;
            split2(vx, vy, hi, lo);
            *(uint32_t*)(g_Oh + ro + nt * 8 + 2 * t) = hi;
            *(uint32_t*)(g_Ol + ro + nt * 8 + 2 * t) = lo;
        }
    }
}

// ---------------------------------------------------------------------------
extern "C" void kernel_launch(void* const* d_in, const int* in_sizes, int n_in,
                              void* d_out, int out_size)
{
    const float* x  = (const float*)d_in[0];
    const float* Wq = (const float*)d_in[1];
    const float* bq = (const float*)d_in[2];
    const float* Wk = (const float*)d_in[3];
    const float* bk = (const float*)d_in[4];
    const float* Wv = (const float*)d_in[5];
    const float* bv = (const float*)d_in[6];
    const float* Wo = (const float*)d_in[7];
    const float* bo = (const float*)d_in[8];
    float* out = (float*)d_out;

    static int attr_set = 0;
    if (!attr_set) {
        cudaFuncSetAttribute(gemm_bf16x2,
                             cudaFuncAttributeMaxDynamicSharedMemorySize,
                             G_SMEM);
        cudaFuncSetAttribute(attn_bf16x2,
                             cudaFuncAttributeMaxDynamicSharedMemorySize,
                             ATT_SMEM);
        attr_set = 1;
    }

    // Split fp32 -> bf16 hi/lo planes
    const int nx4 = MROWS * DMODEL / 4;
    const int nw4 = DMODEL * DMODEL / 4;
    split_kernel<<<(nx4 + 255) / 256, 256>>>(x, 0, nx4);
    split_kernel<<<(nw4 + 255) / 256, 256>>>(Wq, 1, nw4);
    split_kernel<<<(nw4 + 255) / 256, 256>>>(Wk, 2, nw4);
    split_kernel<<<(nw4 + 255) / 256, 256>>>(Wv, 3, nw4);
    split_kernel<<<(nw4 + 255) / 256, 256>>>(Wo, 4, nw4);

    dim3 ggrid(DMODEL / 128, MROWS / 128);   // (8, 32)
    gemm_bf16x2<<<ggrid, 256, G_SMEM>>>(bq, nullptr, 1);
    gemm_bf16x2<<<ggrid, 256, G_SMEM>>>(bk, nullptr, 2);
    gemm_bf16x2<<<ggrid, 256, G_SMEM>>>(bv, nullptr, 3);

    attn_bf16x2<<<dim3(SEQ / 128, BATCH * HEADS), 256, ATT_SMEM>>>();

    gemm_bf16x2<<<ggrid, 256, G_SMEM>>>(bo, out, 0);
}

// round 5
// speedup vs baseline: 2.2980x; 1.0416x over previous
#include <cuda_runtime.h>
#include <cuda_bf16.h>
#include <cstdint>

// Problem constants
#define BATCH   2
#define HEADS   16
#define SEQ     2048
#define HD      64
#define DMODEL  1024
#define MROWS   (BATCH * SEQ)   // 4096

// ===========================================================================
// Global scratch (allocation-free rule: __device__ globals). bf16 hi/lo planes.
// ===========================================================================
__device__ __nv_bfloat16 g_xh[MROWS * DMODEL], g_xl[MROWS * DMODEL];
__device__ __nv_bfloat16 g_Wqh[DMODEL * DMODEL], g_Wql[DMODEL * DMODEL];
__device__ __nv_bfloat16 g_Wkh[DMODEL * DMODEL], g_Wkl[DMODEL * DMODEL];
__device__ __nv_bfloat16 g_Wvh[DMODEL * DMODEL], g_Wvl[DMODEL * DMODEL];
__device__ __nv_bfloat16 g_Woh[DMODEL * DMODEL], g_Wol[DMODEL * DMODEL];
__device__ __nv_bfloat16 g_Qh[MROWS * DMODEL], g_Ql[MROWS * DMODEL];  // [B,H,S,HD]
__device__ __nv_bfloat16 g_Kh[MROWS * DMODEL], g_Kl[MROWS * DMODEL];
__device__ __nv_bfloat16 g_Vh[MROWS * DMODEL], g_Vl[MROWS * DMODEL];
__device__ __nv_bfloat16 g_Oh[MROWS * DMODEL], g_Ol[MROWS * DMODEL];  // [B,S,D]

// ===========================================================================
// PTX helpers
// ===========================================================================
__device__ __forceinline__ void mma_bf16(float* c, const uint32_t* a,
                                         uint32_t b0, uint32_t b1) {
    asm volatile(
        "mma.sync.aligned.m16n8k16.row.col.f32.bf16.bf16.f32 "
        "{%0,%1,%2,%3}, {%4,%5,%6,%7}, {%8,%9}, {%0,%1,%2,%3};\n"
        : "+f"(c[0]), "+f"(c[1]), "+f"(c[2]), "+f"(c[3])
        : "r"(a[0]), "r"(a[1]), "r"(a[2]), "r"(a[3]), "r"(b0), "r"(b1));
}

__device__ __forceinline__ void ldsm_x4(uint32_t* r, uint32_t addr) {
    asm volatile(
        "ldmatrix.sync.aligned.m8n8.x4.shared.b16 {%0,%1,%2,%3}, [%4];"
        : "=r"(r[0]), "=r"(r[1]), "=r"(r[2]), "=r"(r[3]) : "r"(addr));
}

__device__ __forceinline__ void ldsm_x4_t(uint32_t* r, uint32_t addr) {
    asm volatile(
        "ldmatrix.sync.aligned.m8n8.x4.trans.shared.b16 {%0,%1,%2,%3}, [%4];"
        : "=r"(r[0]), "=r"(r[1]), "=r"(r[2]), "=r"(r[3]) : "r"(addr));
}

__device__ __forceinline__ uint32_t smem_u32(const void* p) {
    uint32_t a;
    asm("{ .reg .u64 t; cvta.to.shared.u64 t, %1; cvt.u32.u64 %0, t; }"
        : "=r"(a) : "l"(p));
    return a;
}

__device__ __forceinline__ void cp_async16(uint32_t dst, const void* src) {
    asm volatile("cp.async.cg.shared.global [%0], [%1], 16;"
                 :: "r"(dst), "l"(src));
}
__device__ __forceinline__ void cp_commit() {
    asm volatile("cp.async.commit_group;");
}
template <int N> __device__ __forceinline__ void cp_wait() {
    asm volatile("cp.async.wait_group %0;" :: "n"(N));
}

__device__ __forceinline__ void split2(float x, float y,
                                       uint32_t& hi, uint32_t& lo) {
    __nv_bfloat16 hx = __float2bfloat16(x);
    __nv_bfloat16 hy = __float2bfloat16(y);
    __nv_bfloat162 h = __halves2bfloat162(hx, hy);
    __nv_bfloat162 l = __halves2bfloat162(
        __float2bfloat16(x - __bfloat162float(hx)),
        __float2bfloat16(y - __bfloat162float(hy)));
    hi = *(uint32_t*)&h;
    lo = *(uint32_t*)&l;
}

// ===========================================================================
// Split fp32 tensor -> bf16 hi/lo planes. which: 0=x 1=Wq 2=Wk 3=Wv 4=Wo
// ===========================================================================
__global__ __launch_bounds__(256) void split_kernel(
    const float* __restrict__ src, int which, int n4)
{
    __nv_bfloat16 *hi, *lo;
    switch (which) {
        case 0: hi = g_xh;  lo = g_xl;  break;
        case 1: hi = g_Wqh; lo = g_Wql; break;
        case 2: hi = g_Wkh; lo = g_Wkl; break;
        case 3: hi = g_Wvh; lo = g_Wvl; break;
        default: hi = g_Woh; lo = g_Wol; break;
    }
    int i = blockIdx.x * blockDim.x + threadIdx.x;
    if (i >= n4) return;
    float4 v = ((const float4*)src)[i];
    uint32_t h0, l0, h1, l1;
    split2(v.x, v.y, h0, l0);
    split2(v.z, v.w, h1, l1);
    ((uint32_t*)hi)[2 * i + 0] = h0;
    ((uint32_t*)hi)[2 * i + 1] = h1;
    ((uint32_t*)lo)[2 * i + 0] = l0;
    ((uint32_t*)lo)[2 * i + 1] = l1;
}

// ===========================================================================
// bf16x2 GEMM: out = A[M,K] @ W[N,K]^T + bias  (M=4096, N=K=1024)
// CTA 128x128, BK=32, 256 threads (8 warps 4m x 2n). ldmatrix.x4 fragments.
// final=0: z=0/1/2 -> Wq/Wk/Wv, A=x planes, write Q/K/V planes [B,H,S,HD]
// final=1: A=g_O planes, W=Wo, write fp32 out [M,N]
// ===========================================================================
#define GPLB 10240                 // plane bytes: 128 rows * 40 bf16 * 2
#define GSTAGE (4 * GPLB)          // 40960
#define G_SMEM (2 * GSTAGE)        // 81920

__global__ __launch_bounds__(256, 2) void gemm_bf16x2(
    const float* __restrict__ bq, const float* __restrict__ bk,
    const float* __restrict__ bv, const float* __restrict__ bo,
    float* __restrict__ out, int final_)
{
    extern __shared__ char sm[];
    const uint32_t sbase = smem_u32(sm);

    const int mode = final_ ? 0 : (int)blockIdx.z + 1;
    const __nv_bfloat16 *Agh, *Agl, *Bgh, *Bgl;
    const float* bias;
    if (mode == 0)      { Agh = g_Oh; Agl = g_Ol; Bgh = g_Woh; Bgl = g_Wol; bias = bo; }
    else if (mode == 1) { Agh = g_xh; Agl = g_xl; Bgh = g_Wqh; Bgl = g_Wql; bias = bq; }
    else if (mode == 2) { Agh = g_xh; Agl = g_xl; Bgh = g_Wkh; Bgl = g_Wkl; bias = bk; }
    else                { Agh = g_xh; Agl = g_xl; Bgh = g_Wvh; Bgl = g_Wvl; bias = bv; }

    const int tid  = threadIdx.x;
    const int lane = tid & 31;
    const int wid  = tid >> 5;
    const int wm   = wid & 3;
    const int wn   = wid >> 2;
    const int g    = lane >> 2;
    const int t    = lane & 3;
    const int lr   = lane & 15;
    const int lk   = (lane >> 4) << 3;
    const int row0 = blockIdx.y * 128;
    const int col0 = blockIdx.x * 128;

    float acc[2][8][4];
#pragma unroll
    for (int i = 0; i < 2; i++)
#pragma unroll
        for (int j = 0; j < 8; j++)
#pragma unroll
            for (int q = 0; q < 4; q++) acc[i][j][q] = 0.0f;

    auto ld_stage = [&](int s, int kt) {
        const int kb = kt * 32;
        const uint32_t sb2 = sbase + s * GSTAGE;
#pragma unroll
        for (int i = 0; i < 2; i++) {
            int f = tid + i * 256;
            int r = f >> 2;
            int c = (f & 3) * 8;
            uint32_t o2 = (uint32_t)(r * 80 + c * 2);
            size_t ga = (size_t)(row0 + r) * DMODEL + kb + c;
            size_t gb = (size_t)(col0 + r) * DMODEL + kb + c;
            cp_async16(sb2 + o2,             Agh + ga);
            cp_async16(sb2 + GPLB + o2,      Agl + ga);
            cp_async16(sb2 + 2 * GPLB + o2,  Bgh + gb);
            cp_async16(sb2 + 3 * GPLB + o2,  Bgl + gb);
        }
    };

    ld_stage(0, 0);
    cp_commit();

    const int NS = DMODEL / 32;   // 32
    for (int kt = 0; kt < NS; kt++) {
        if (kt + 1 < NS) {
            ld_stage((kt + 1) & 1, kt + 1);
            cp_commit();
            cp_wait<1>();
        } else {
            cp_wait<0>();
        }
        __syncthreads();

        const uint32_t stb = sbase + (kt & 1) * GSTAGE;

#pragma unroll
        for (int kk = 0; kk < 2; kk++) {
            uint32_t ah[2][4], al[2][4];
#pragma unroll
            for (int mt = 0; mt < 2; mt++) {
                uint32_t ao = stb +
                    (uint32_t)(((wm * 32 + mt * 16 + lr) * 40 + kk * 16 + lk) * 2);
                ldsm_x4(ah[mt], ao);
                ldsm_x4(al[mt], ao + GPLB);
            }
#pragma unroll
            for (int np = 0; np < 4; np++) {
                uint32_t bh[4], bl[4];
                uint32_t bo_ = stb + 2 * GPLB +
                    (uint32_t)(((wn * 64 + np * 16 + lr) * 40 + kk * 16 + lk) * 2);
                ldsm_x4(bh, bo_);
                ldsm_x4(bl, bo_ + GPLB);
#pragma unroll
                for (int mt = 0; mt < 2; mt++) {
                    mma_bf16(acc[mt][2 * np],     ah[mt], bh[0], bh[2]);
                    mma_bf16(acc[mt][2 * np],     ah[mt], bl[0], bl[2]);
                    mma_bf16(acc[mt][2 * np],     al[mt], bh[0], bh[2]);
                    mma_bf16(acc[mt][2 * np + 1], ah[mt], bh[1], bh[3]);
                    mma_bf16(acc[mt][2 * np + 1], ah[mt], bl[1], bl[3]);
                    mma_bf16(acc[mt][2 * np + 1], al[mt], bh[1], bh[3]);
                }
            }
        }
        __syncthreads();
    }

    // Epilogue
    __nv_bfloat16* Dh = (mode == 1) ? g_Qh : (mode == 2) ? g_Kh : g_Vh;
    __nv_bfloat16* Dl = (mode == 1) ? g_Ql : (mode == 2) ? g_Kl : g_Vl;
#pragma unroll
    for (int mt = 0; mt < 2; mt++) {
#pragma unroll
        for (int h = 0; h < 2; h++) {
            const int m = row0 + wm * 32 + mt * 16 + g + h * 8;
            const int b_ = m >> 11;
            const int s_ = m & 2047;
#pragma unroll
            for (int nt = 0; nt < 8; nt++) {
                const int n = col0 + wn * 64 + nt * 8 + 2 * t;
                float vx = acc[mt][nt][h * 2 + 0] + bias[n + 0];
                float vy = acc[mt][nt][h * 2 + 1] + bias[n + 1];
                if (mode == 0) {
                    float2 v; v.x = vx; v.y = vy;
                    *(float2*)(out + (size_t)m * DMODEL + n) = v;
                } else {
                    const int hh = n >> 6, d = n & 63;
                    size_t idx = (((size_t)(b_ * HEADS + hh)) * SEQ + s_) * HD + d;
                    uint32_t hi, lo;
                    split2(vx, vy, hi, lo);
                    *(uint32_t*)(Dh + idx) = hi;
                    *(uint32_t*)(Dl + idx) = lo;
                }
            }
        }
    }
}

// ===========================================================================
// Flash attention, bf16x2 mma, P & Q in registers. Grid (SEQ/128, B*H),
// 256 threads (8 warps), 2 CTAs/SM. Smem = K/V hi/lo double-buffer only.
// Stage layout: Kh[64][72] | Kl | Vh | Vl  (9216 B each, 36864 B per stage)
// ===========================================================================
#define AST(st) ((st) * 36864)
#define ATT_SMEM 73728

__global__ __launch_bounds__(256, 2) void attn_bf16x2()
{
    extern __shared__ char sm[];
    const uint32_t sb = smem_u32(sm);

    const int tid  = threadIdx.x;
    const int lane = tid & 31;
    const int wid  = tid >> 5;
    const int g    = lane >> 2;
    const int t    = lane & 3;
    const int lr   = lane & 15;
    const int lh   = lane >> 4;        // 0/1
    const int qt   = blockIdx.x;       // 0..15
    const int bh   = blockIdx.y;       // 0..31

    // ---- Q fragments in registers (loaded once, scale folded in) ----
    uint32_t qh[4][4], ql[4][4];
    {
        const size_t base = ((size_t)bh * SEQ + qt * 128 + wid * 16) * HD;
        const __nv_bfloat16* Qh = g_Qh + base;
        const __nv_bfloat16* Ql = g_Ql + base;
#pragma unroll
        for (int kk = 0; kk < 4; kk++) {
            const int d0 = kk * 16 + 2 * t;
            qh[kk][0] = *(const uint32_t*)(Qh + g * HD + d0);
            qh[kk][1] = *(const uint32_t*)(Qh + (g + 8) * HD + d0);
            qh[kk][2] = *(const uint32_t*)(Qh + g * HD + d0 + 8);
            qh[kk][3] = *(const uint32_t*)(Qh + (g + 8) * HD + d0 + 8);
            ql[kk][0] = *(const uint32_t*)(Ql + g * HD + d0);
            ql[kk][1] = *(const uint32_t*)(Ql + (g + 8) * HD + d0);
            ql[kk][2] = *(const uint32_t*)(Ql + g * HD + d0 + 8);
            ql[kk][3] = *(const uint32_t*)(Ql + (g + 8) * HD + d0 + 8);
        }
    }

    auto ld_kv = [&](int st, int ck) {
        const size_t go = ((size_t)bh * SEQ + (size_t)ck * 64) * HD;
        const uint32_t base = sb + AST(st);
#pragma unroll
        for (int i = 0; i < 2; i++) {
            int f = tid + i * 256;
            int r = f >> 3, c = f & 7;
            uint32_t o2 = (uint32_t)(r * 144 + c * 16);
            size_t gi = go + r * 64 + c * 8;
            cp_async16(base + o2,          g_Kh + gi);
            cp_async16(base + 9216 + o2,   g_Kl + gi);
            cp_async16(base + 18432 + o2,  g_Vh + gi);
            cp_async16(base + 27648 + o2,  g_Vl + gi);
        }
    };

    ld_kv(0, 0); cp_commit();
    ld_kv(1, 1); cp_commit();

    float o[8][4];
#pragma unroll
    for (int nt = 0; nt < 8; nt++)
#pragma unroll
        for (int q = 0; q < 4; q++) o[nt][q] = 0.0f;
    float mrow[2] = {-1e30f, -1e30f};
    float lrow[2] = {0.0f, 0.0f};
    const float scale = 0.125f;

    for (int ck = 0; ck < SEQ / 64; ck++) {
        if (ck >= SEQ / 64 - 2) cp_wait<0>(); else cp_wait<1>();
        __syncthreads();

        const uint32_t kpl = sb + AST(ck & 1);
        const uint32_t vpl = kpl + 18432;

        // ---- QK^T ----
        float s[8][4];
#pragma unroll
        for (int nt = 0; nt < 8; nt++)
#pragma unroll
            for (int q = 0; q < 4; q++) s[nt][q] = 0.0f;

#pragma unroll
        for (int kk = 0; kk < 4; kk++) {
#pragma unroll
            for (int np = 0; np < 4; np++) {
                uint32_t kbh[4], kbl[4];
                uint32_t ko = kpl +
                    (uint32_t)(((np * 16 + lr) * 72 + kk * 16 + lh * 8) * 2);
                ldsm_x4(kbh, ko);
                ldsm_x4(kbl, ko + 9216);
                mma_bf16(s[2 * np],     qh[kk], kbh[0], kbh[2]);
                mma_bf16(s[2 * np],     qh[kk], kbl[0], kbl[2]);
                mma_bf16(s[2 * np],     ql[kk], kbh[0], kbh[2]);
                mma_bf16(s[2 * np + 1], qh[kk], kbh[1], kbh[3]);
                mma_bf16(s[2 * np + 1], qh[kk], kbl[1], kbl[3]);
                mma_bf16(s[2 * np + 1], ql[kk], kbh[1], kbh[3]);
            }
        }

        // ---- online softmax (rows g, g+8; warp-local over t lanes) ----
#pragma unroll
        for (int nt = 0; nt < 8; nt++)
#pragma unroll
            for (int q = 0; q < 4; q++) s[nt][q] *= scale;

#pragma unroll
        for (int h = 0; h < 2; h++) {
            float mx = -1e30f;
#pragma unroll
            for (int nt = 0; nt < 8; nt++) {
                mx = fmaxf(mx, s[nt][h * 2 + 0]);
                mx = fmaxf(mx, s[nt][h * 2 + 1]);
            }
            mx = fmaxf(mx, __shfl_xor_sync(0xffffffffu, mx, 1));
            mx = fmaxf(mx, __shfl_xor_sync(0xffffffffu, mx, 2));
            const float mnew  = fmaxf(mrow[h], mx);
            const float alpha = __expf(mrow[h] - mnew);
            float rsum = 0.0f;
#pragma unroll
            for (int nt = 0; nt < 8; nt++) {
                float p0 = __expf(s[nt][h * 2 + 0] - mnew);
                float p1 = __expf(s[nt][h * 2 + 1] - mnew);
                s[nt][h * 2 + 0] = p0;
                s[nt][h * 2 + 1] = p1;
                rsum += p0 + p1;
            }
            rsum += __shfl_xor_sync(0xffffffffu, rsum, 1);
            rsum += __shfl_xor_sync(0xffffffffu, rsum, 2);
            lrow[h] = lrow[h] * alpha + rsum;
            mrow[h] = mnew;
#pragma unroll
            for (int nt = 0; nt < 8; nt++) {
                o[nt][h * 2 + 0] *= alpha;
                o[nt][h * 2 + 1] *= alpha;
            }
        }

        // ---- O += P @ V  (P repacked C->A frags in registers) ----
#pragma unroll
        for (int kk = 0; kk < 4; kk++) {
            uint32_t ph[4], pl[4];
            split2(s[2 * kk][0],     s[2 * kk][1],     ph[0], pl[0]);
            split2(s[2 * kk][2],     s[2 * kk][3],     ph[1], pl[1]);
            split2(s[2 * kk + 1][0], s[2 * kk + 1][1], ph[2], pl[2]);
            split2(s[2 * kk + 1][2], s[2 * kk + 1][3], ph[3], pl[3]);
#pragma unroll
            for (int np = 0; np < 4; np++) {
                uint32_t vbh[4], vbl[4];
                uint32_t vo = vpl +
                    (uint32_t)((kk * 16 + lr) * 144 + np * 32 + lh * 16);
                ldsm_x4_t(vbh, vo);
                ldsm_x4_t(vbl, vo + 9216);
                mma_bf16(o[2 * np],     ph, vbh[0], vbh[1]);
                mma_bf16(o[2 * np],     ph, vbl[0], vbl[1]);
                mma_bf16(o[2 * np],     pl, vbh[0], vbh[1]);
                mma_bf16(o[2 * np + 1], ph, vbh[2], vbh[3]);
                mma_bf16(o[2 * np + 1], ph, vbl[2], vbl[3]);
                mma_bf16(o[2 * np + 1], pl, vbh[2], vbh[3]);
            }
        }
        __syncthreads();
        if (ck + 2 < SEQ / 64) { ld_kv(ck & 1, ck + 2); cp_commit(); }
    }

    // ---- epilogue: split & write to g_O planes [B,S,D] ----
    const int b_ = bh >> 4;
    const int h_ = bh & 15;
#pragma unroll
    for (int h = 0; h < 2; h++) {
        const float inv = 1.0f / lrow[h];
        const int srow = qt * 128 + wid * 16 + g + h * 8;
        const size_t ro = ((size_t)(b_ * SEQ + srow)) * DMODEL + h_ * 64;
#pragma unroll
        for (int nt = 0; nt < 8; nt++) {
            float vx = o[nt][h * 2 + 0] * inv;
            float vy = o[nt][h * 2 + 1] * inv;
            uint32_t hi, lo;
            split2(vx, vy, hi, lo);
            *(uint32_t*)(g_Oh + ro + nt * 8 + 2 * t) = hi;
            *(uint32_t*)(g_Ol + ro + nt * 8 + 2 * t) = lo;
        }
    }
}

// ---------------------------------------------------------------------------
extern "C" void kernel_launch(void* const* d_in, const int* in_sizes, int n_in,
                              void* d_out, int out_size)
{
    const float* x  = (const float*)d_in[0];
    const float* Wq = (const float*)d_in[1];
    const float* bq = (const float*)d_in[2];
    const float* Wk = (const float*)d_in[3];
    const float* bk = (const float*)d_in[4];
    const float* Wv = (const float*)d_in[5];
    const float* bv = (const float*)d_in[6];
    const float* Wo = (const float*)d_in[7];
    const float* bo = (const float*)d_in[8];
    float* out = (float*)d_out;

    static int attr_set = 0;
    if (!attr_set) {
        cudaFuncSetAttribute(gemm_bf16x2,
                             cudaFuncAttributeMaxDynamicSharedMemorySize,
                             G_SMEM);
        cudaFuncSetAttribute(attn_bf16x2,
                             cudaFuncAttributeMaxDynamicSharedMemorySize,
                             ATT_SMEM);
        attr_set = 1;
    }

    // Split fp32 -> bf16 hi/lo planes
    const int nx4 = MROWS * DMODEL / 4;
    const int nw4 = DMODEL * DMODEL / 4;
    split_kernel<<<(nx4 + 255) / 256, 256>>>(x, 0, nx4);
    split_kernel<<<(nw4 + 255) / 256, 256>>>(Wq, 1, nw4);
    split_kernel<<<(nw4 + 255) / 256, 256>>>(Wk, 2, nw4);
    split_kernel<<<(nw4 + 255) / 256, 256>>>(Wv, 3, nw4);
    split_kernel<<<(nw4 + 255) / 256, 256>>>(Wo, 4, nw4);

    // Fused QKV projections (z selects Wq/Wk/Wv)
    gemm_bf16x2<<<dim3(DMODEL / 128, MROWS / 128, 3), 256, G_SMEM>>>(
        bq, bk, bv, nullptr, nullptr, 0);

    attn_bf16x2<<<dim3(SEQ / 128, BATCH * HEADS), 256, ATT_SMEM>>>();

    // Output projection
    gemm_bf16x2<<<dim3(DMODEL / 128, MROWS / 128, 1), 256, G_SMEM>>>(
        nullptr, nullptr, nullptr, bo, out, 1);
}